// round 13
// baseline (speedup 1.0000x reference)
#include <cuda_runtime.h>
#include <cuda_fp16.h>
#include <cstdint>

#define BS 16
#define SP_IN 512
#define SP_OUT 256
#define DN_IN 128
#define N_STK 256
#define N_BEF 512
#define INV_SQRT_BN 0.99999500003749973f

// ---- scratch ----
__device__ float g_coorT[BS * 128 * N_STK];
__device__ float g_spT[BS * N_STK * SP_IN];
__device__ float g_wspT[SP_IN * SP_OUT];
__device__ float g_normM[BS * N_STK];
__device__ float g_normB[BS * N_BEF];
__device__ int2   g_nn[BS * N_BEF];
__device__ float2 g_wt[BS * N_BEF];
__device__ __half g_DpH[(size_t)BS * 16386 * 128];   // padded interp seq, HALF, k-slot remapped rows
__device__ unsigned g_AfragH[2 * 16384];             // [par][(s*8+mt)*32+lane]*4+r, half2 bits

// ---- helpers ----
__device__ __forceinline__ unsigned long long pack2(float a, float b) {
    unsigned long long r; asm("mov.b64 %0, {%1, %2};" : "=l"(r) : "f"(a), "f"(b)); return r;
}
__device__ __forceinline__ float2 unpack2f(unsigned long long v) {
    float2 r; asm("mov.b64 {%0, %1}, %2;" : "=f"(r.x), "=f"(r.y) : "l"(v)); return r;
}
__device__ __forceinline__ void ffma2(unsigned long long &acc, unsigned long long a, unsigned long long b) {
    asm("fma.rn.f32x2 %0, %1, %2, %0;" : "+l"(acc) : "l"(a), "l"(b));
}
__device__ __forceinline__ unsigned mono(float f) {
    unsigned u = __float_as_uint(f); return (u & 0x80000000u) ? ~u : (u | 0x80000000u);
}
__device__ __forceinline__ float invmono(unsigned u) {
    unsigned v = (u & 0x80000000u) ? (u & 0x7FFFFFFFu) : ~u; return __uint_as_float(v);
}
__device__ __forceinline__ float gelu_tanh(float x) {
    float g = 0.7978845608028654f * x * fmaf(0.044715f, x * x, 1.0f);
    float e = __expf(2.0f * g);
    return 0.5f * x * (2.0f - 2.0f / (e + 1.0f));
}
__device__ __forceinline__ void mma_f16(float* d, const uint32_t* a, uint32_t b0, uint32_t b1) {
    asm volatile("mma.sync.aligned.m16n8k16.row.col.f32.f16.f16.f32 "
                 "{%0,%1,%2,%3}, {%4,%5,%6,%7}, {%8,%9}, {%0,%1,%2,%3};"
                 : "+f"(d[0]), "+f"(d[1]), "+f"(d[2]), "+f"(d[3])
                 : "r"(a[0]), "r"(a[1]), "r"(a[2]), "r"(a[3]), "r"(b0), "r"(b1));
}
__device__ __forceinline__ uint32_t smem_u32(const void* p) {
    uint32_t a; asm("{ .reg .u64 t; cvta.to.shared.u64 t, %1; cvt.u32.u64 %0, t; }" : "=r"(a) : "l"(p)); return a;
}
__device__ __forceinline__ void cp_async16(uint32_t dst, const void* src) {
    asm volatile("cp.async.cg.shared.global [%0], [%1], 16;" :: "r"(dst), "l"(src));
}
#define CP_COMMIT() asm volatile("cp.async.commit_group;" ::: "memory")
#define CP_WAIT(n)  asm volatile("cp.async.wait_group %0;" :: "n"(n) : "memory")

// ---- merged: transpose stk_coor + both norm sets ----
__global__ void k_pre(const float* __restrict__ coor, const float* __restrict__ bef) {
    if (blockIdx.z < 16) {
        __shared__ float tile[32][33];
        int b = blockIdx.z;
        const float* s = coor + (size_t)b * 256 * 128;
        float* d = g_coorT + (size_t)b * 256 * 128;
        int r0 = blockIdx.y * 32, c0 = (blockIdx.x & 3) * 32;
        int tx = threadIdx.x & 31, ty = threadIdx.x >> 5;
#pragma unroll
        for (int k = 0; k < 32; k += 8)
            tile[ty + k][tx] = s[(size_t)(r0 + ty + k) * 128 + c0 + tx];
        __syncthreads();
#pragma unroll
        for (int k = 0; k < 32; k += 8)
            d[(size_t)(c0 + ty + k) * 256 + r0 + tx] = tile[tx][ty + k];
    } else {
        int bid = blockIdx.y * 4 + blockIdx.x;
        int warp = bid * 8 + (threadIdx.x >> 5);
        int lane = threadIdx.x & 31;
        for (int w = warp; w < BS * N_STK + BS * N_BEF; w += 256) {
            const float* src; float* dst;
            if (w < BS * N_STK) { src = coor + (size_t)w * 128; dst = g_normM + w; }
            else { int v2 = w - BS * N_STK; src = bef + (size_t)v2 * 128; dst = g_normB + v2; }
            float4 v = ((const float4*)src)[lane];
            float s = v.x * v.x + v.y * v.y + v.z * v.z + v.w * v.w;
#pragma unroll
            for (int off = 16; off; off >>= 1) s += __shfl_xor_sync(0xffffffffu, s, off);
            if (!lane) *dst = s;
        }
    }
}

// ---- top-2 neighbors ----
__global__ __launch_bounds__(256, 4) void k_topk(const float* __restrict__ bef) {
    __shared__ float befs[16 * 128];
    __shared__ unsigned long long keys[16][264];
    int n0 = blockIdx.x * 16, b = blockIdx.y, tid = threadIdx.x;
    for (int idx = tid; idx < 16 * 128; idx += 256)
        befs[idx] = bef[((size_t)b * N_BEF + n0) * 128 + idx];
    __syncthreads();
    int m = tid;
    float acc[16];
#pragma unroll
    for (int j = 0; j < 16; j++) acc[j] = 0.0f;
    const float* cT = g_coorT + (size_t)b * 128 * N_STK + m;
    for (int cb = 0; cb < 128; cb += 32) {
        float part[16];
#pragma unroll
        for (int j = 0; j < 16; j++) part[j] = 0.0f;
        for (int c0 = cb; c0 < cb + 32; c0 += 4) {
            float v0 = cT[(c0 + 0) * N_STK], v1 = cT[(c0 + 1) * N_STK];
            float v2 = cT[(c0 + 2) * N_STK], v3 = cT[(c0 + 3) * N_STK];
#pragma unroll
            for (int j = 0; j < 16; j++) {
                float4 bf = *(const float4*)&befs[j * 128 + c0];
                part[j] = fmaf(bf.x, v0, part[j]); part[j] = fmaf(bf.y, v1, part[j]);
                part[j] = fmaf(bf.z, v2, part[j]); part[j] = fmaf(bf.w, v3, part[j]);
            }
        }
#pragma unroll
        for (int j = 0; j < 16; j++) acc[j] += part[j];
    }
    float nm = g_normM[b * N_STK + m];
#pragma unroll
    for (int j = 0; j < 16; j++) {
        float d2v = g_normB[b * N_BEF + n0 + j] + nm - 2.0f * acc[j];
        keys[j][m] = ((unsigned long long)mono(d2v) << 8) | (unsigned)m;
    }
    __syncthreads();
    int wid = tid >> 5, lane = tid & 31;
#pragma unroll
    for (int jj = 0; jj < 2; jj++) {
        int j = wid + jj * 8;
        unsigned long long k1 = 0xFFFFFFFFFFFFFFFFull, k2 = k1;
#pragma unroll
        for (int t = 0; t < 8; t++) {
            unsigned long long kv = keys[j][lane * 8 + t];
            if (kv < k1) { k2 = k1; k1 = kv; }
            else if (kv < k2) { k2 = kv; }
        }
#pragma unroll
        for (int off = 16; off; off >>= 1) {
            unsigned long long o1 = __shfl_xor_sync(0xffffffffu, k1, off);
            unsigned long long o2 = __shfl_xor_sync(0xffffffffu, k2, off);
            unsigned long long n1 = k1 < o1 ? k1 : o1;
            unsigned long long hi = k1 < o1 ? o1 : k1;
            unsigned long long lo2 = k2 < o2 ? k2 : o2;
            k2 = hi < lo2 ? hi : lo2;
            k1 = n1;
        }
        if (lane == 0) {
            float d0 = invmono((unsigned)(k1 >> 8)), d1 = invmono((unsigned)(k2 >> 8));
            float r0 = 1.0f / (d0 + 1e-8f), r1 = 1.0f / (d1 + 1e-8f), s = r0 + r1;
            g_nn[b * N_BEF + n0 + j] = make_int2((int)(k1 & 0xFF), (int)(k2 & 0xFF));
            g_wt[b * N_BEF + n0 + j] = make_float2(r0 / s, r1 / s);
        }
    }
}

// slot remap: old c-pair index c2 (=4s+tg) -> new 4B slot (s>>1)*8 + tg*2 + (s&1)
__device__ __forceinline__ int slot_remap(int c2) {
    int s_ = c2 >> 2, tg_ = c2 & 3;
    return (s_ >> 1) * 8 + tg_ * 2 + (s_ & 1);
}

// ---- prepD (half, remapped rows) + prepA merged ----
__global__ __launch_bounds__(256) void k_prep(const float* __restrict__ dense,
                                              const float* __restrict__ w_ct) {
    if (blockIdx.y == 16) {
        if (blockIdx.x >= 128) return;
        int idx = blockIdx.x * 256 + threadIdx.x;       // 0..32767
        int par = idx >> 14, t = idx & 16383;
        int r = t & 3, lane = (t >> 2) & 31, mt = (t >> 7) & 7, s = t >> 10;
        int g = lane >> 2, tg = lane & 3;
        int m = mt * 16 + g + ((r & 1) ? 8 : 0);
        int q = (r >= 2) ? 1 : 0;
        int c0 = s * 8 + 2 * tg;
        int tap = par ? (q ? 0 : 2) : (q ? 1 : 3);
        __half h0 = __float2half_rn(w_ct[c0 * 512 + m * 4 + tap]);
        __half h1 = __float2half_rn(w_ct[(c0 + 1) * 512 + m * 4 + tap]);
        __half2 hh = __halves2half2(h0, h1);
        g_AfragH[par * 16384 + t] = *(unsigned*)&hh;
        return;
    }
    __shared__ float sm[128 * 33];
    int n = blockIdx.x, b = blockIdx.y, tid = threadIdx.x;
    int2 id = g_nn[b * N_BEF + n]; float2 wt = g_wt[b * N_BEF + n];
    const float* dB = dense + (size_t)b * DN_IN * 8192;
    int w = tid >> 5, p = tid & 31;
    for (int c = w; c < 128; c += 8)
        sm[c * 33 + p] = wt.x * dB[c * 8192 + id.x * 32 + p] + wt.y * dB[c * 8192 + id.y * 32 + p];
    __syncthreads();
    __half2* DpRow = (__half2*)(g_DpH + ((size_t)b * 16386 + 1 + n * 32) * 128);
    for (int i = tid; i < 32 * 64; i += 256) {
        int pp = i >> 6, c2 = i & 63;
        DpRow[pp * 64 + slot_remap(c2)] =
            __floats2half2_rn(sm[(2 * c2) * 33 + pp], sm[(2 * c2 + 1) * 33 + pp]);
    }
    if (n == 0 && tid < 64)
        ((__half2*)(g_DpH + (size_t)b * 16386 * 128))[slot_remap(tid)] =
            __floats2half2_rn(sm[(2 * tid) * 33], sm[(2 * tid + 1) * 33]);
    if (n == 511 && tid < 64)
        ((__half2*)(g_DpH + ((size_t)b * 16386 + 16385) * 128))[slot_remap(tid)] =
            __floats2half2_rn(sm[(2 * tid) * 33 + 31], sm[(2 * tid + 1) * 33 + 31]);
}

// ---- dense GEMM: mma.sync fp16, persistent, cp.async x2, LDS.64 B loads ----
#define STGB 272
#define STG_BYTES (66 * STGB)
#define SMEM_BYTES (65536 + 2 * STG_BYTES)
__global__ void __launch_bounds__(256, 2) k_gemm(const float* __restrict__ b_ct,
                                                 const float* __restrict__ gam,
                                                 const float* __restrict__ bet,
                                                 float* __restrict__ out) {
    extern __shared__ char smc[];
    uint4* Af4 = (uint4*)smc;
    char* stg = smc + 65536;
    int tid = threadIdx.x, wid = tid >> 5, lane = tid & 31;
    int warpM = wid & 3, warpN = wid >> 2;
    int g = lane >> 2, tg = lane & 3;
    int par = blockIdx.x & 1, cslot = blockIdx.x >> 1;

    const uint4* Ag = (const uint4*)(g_AfragH + par * 16384);
    for (int i = tid; i < 4096; i += 256) Af4[i] = Ag[i];

    float bs_[2][2], sc_[2][2], bt_[2][2];
#pragma unroll
    for (int mt = 0; mt < 2; mt++)
#pragma unroll
        for (int hh = 0; hh < 2; hh++) {
            int o = warpM * 32 + mt * 16 + g + hh * 8;
            bs_[mt][hh] = b_ct[o];
            sc_[mt][hh] = gam[o] * INV_SQRT_BN;
            bt_[mt][hh] = bet[o];
        }
    int rowb[4];
#pragma unroll
    for (int nt = 0; nt < 4; nt++)
        rowb[nt] = (warpN * 32 + nt * 8 + g + par) * STGB;

    uint32_t stg_u = smem_u32(stg);
    {
        int T = cslot, b = T >> 8, j0 = (T & 255) << 6;
        const char* src = (const char*)(g_DpH + ((size_t)b * 16386 + j0) * 128);
        for (int i = tid; i < 1056; i += 256) {
            int r = i >> 4, ck = i & 15;
            cp_async16(stg_u + r * STGB + ck * 16, src + r * 256 + ck * 16);
        }
        CP_COMMIT();
    }
    __syncthreads();

    int buf = 0;
    for (int T = cslot; T < 4096; T += 148) {
        int b = T >> 8, j0 = (T & 255) << 6;
        int Tn = T + 148;
        if (Tn < 4096) {
            int bn = Tn >> 8, j0n = (Tn & 255) << 6;
            const char* srcn = (const char*)(g_DpH + ((size_t)bn * 16386 + j0n) * 128);
            uint32_t du = stg_u + (buf ^ 1) * STG_BYTES;
            for (int i = tid; i < 1056; i += 256) {
                int r = i >> 4, ck = i & 15;
                cp_async16(du + r * STGB + ck * 16, srcn + r * 256 + ck * 16);
            }
            CP_COMMIT();
            CP_WAIT(1);
        } else {
            CP_WAIT(0);
        }
        __syncthreads();
        const char* sb = stg + buf * STG_BYTES;

        float acc[2][4][4];
#pragma unroll
        for (int mt = 0; mt < 2; mt++)
#pragma unroll
            for (int nt = 0; nt < 4; nt++)
#pragma unroll
                for (int r = 0; r < 4; r++) acc[mt][nt][r] = 0.0f;

#pragma unroll
        for (int s2 = 0; s2 < 8; s2++) {       // 2 k-steps per iteration
            int boff = s2 * 32 + tg * 8;
            uint2 bq0[4], bq1[4];
#pragma unroll
            for (int nt = 0; nt < 4; nt++) {
                bq0[nt] = *(const uint2*)(sb + rowb[nt] + boff);           // q=0 row, steps 2s2, 2s2+1
                bq1[nt] = *(const uint2*)(sb + rowb[nt] + STGB + boff);    // q=1 row
            }
#pragma unroll
            for (int half = 0; half < 2; half++) {
                int s = 2 * s2 + half;
                uint32_t a[2][4];
                *(uint4*)a[0] = Af4[(s * 8 + warpM * 2 + 0) * 32 + lane];
                *(uint4*)a[1] = Af4[(s * 8 + warpM * 2 + 1) * 32 + lane];
#pragma unroll
                for (int mt = 0; mt < 2; mt++)
#pragma unroll
                    for (int nt = 0; nt < 4; nt++)
                        mma_f16(acc[mt][nt], a[mt],
                                half ? bq0[nt].y : bq0[nt].x,
                                half ? bq1[nt].y : bq1[nt].x);
            }
        }

        float* ob = out + ((size_t)b * 128 + warpM * 32 + g) * 32768 + par;
        int jbase = j0 + warpN * 32 + tg * 2;
#pragma unroll
        for (int mt = 0; mt < 2; mt++)
#pragma unroll
            for (int nt = 0; nt < 4; nt++) {
                float* p0 = ob + (size_t)(mt * 16) * 32768 + 2 * (jbase + nt * 8);
                float* p1 = p0 + (size_t)8 * 32768;
                p0[0] = gelu_tanh(fmaf(acc[mt][nt][0] + bs_[mt][0], sc_[mt][0], bt_[mt][0]));
                p0[2] = gelu_tanh(fmaf(acc[mt][nt][1] + bs_[mt][0], sc_[mt][0], bt_[mt][0]));
                p1[0] = gelu_tanh(fmaf(acc[mt][nt][2] + bs_[mt][1], sc_[mt][1], bt_[mt][1]));
                p1[2] = gelu_tanh(fmaf(acc[mt][nt][3] + bs_[mt][1], sc_[mt][1], bt_[mt][1]));
            }
        __syncthreads();
        buf ^= 1;
    }
}

// ---- transpose (sparse branch prep) ----
template<int R, int C, int WHICH>
__global__ void k_transpose(const float* __restrict__ src) {
    float* dstbase = (WHICH == 1) ? g_spT : g_wspT;
    __shared__ float tile[32][33];
    int b = blockIdx.z;
    const float* s = src + (size_t)b * R * C;
    float* d = dstbase + (size_t)b * R * C;
    int r0 = blockIdx.y * 32, c0 = blockIdx.x * 32;
#pragma unroll
    for (int k = 0; k < 32; k += 8)
        tile[threadIdx.y + k][threadIdx.x] = s[(size_t)(r0 + threadIdx.y + k) * C + c0 + threadIdx.x];
    __syncthreads();
#pragma unroll
    for (int k = 0; k < 32; k += 8)
        d[(size_t)(c0 + threadIdx.y + k) * R + r0 + threadIdx.x] = tile[threadIdx.x][threadIdx.y + k];
}

// ---- sparse branch ----
__global__ __launch_bounds__(256) void k_sparse(const float* __restrict__ b_sp,
                                                const float* __restrict__ gam,
                                                const float* __restrict__ bet,
                                                float* __restrict__ out) {
    __shared__ float V[512 * 20];
    __shared__ int2 ii[16];
    __shared__ float2 ww[16];
    int n0 = blockIdx.x * 16, b = blockIdx.y, tid = threadIdx.x;
    if (tid < 16) { ii[tid] = g_nn[b * N_BEF + n0 + tid]; ww[tid] = g_wt[b * N_BEF + n0 + tid]; }
    __syncthreads();
    const float* sT = g_spT + (size_t)b * N_STK * SP_IN;
    for (int idx = tid; idx < 512 * 16; idx += 256) {
        int j = idx >> 9, c = idx & 511;
        int2 id = ii[j]; float2 wt = ww[j];
        V[c * 20 + j] = wt.x * sT[(size_t)id.x * SP_IN + c] + wt.y * sT[(size_t)id.y * SP_IN + c];
    }
    __syncthreads();
    int o = tid;
    unsigned long long acc[8] = {0,0,0,0,0,0,0,0};
#pragma unroll 4
    for (int c = 0; c < 512; c++) {
        float wv = g_wspT[c * SP_OUT + o];
        unsigned long long w2 = pack2(wv, wv);
        const ulonglong2* vr = (const ulonglong2*)&V[c * 20];
        ulonglong2 p0 = vr[0], p1 = vr[1], p2 = vr[2], p3 = vr[3];
        ffma2(acc[0], w2, p0.x); ffma2(acc[1], w2, p0.y);
        ffma2(acc[2], w2, p1.x); ffma2(acc[3], w2, p1.y);
        ffma2(acc[4], w2, p2.x); ffma2(acc[5], w2, p2.y);
        ffma2(acc[6], w2, p3.x); ffma2(acc[7], w2, p3.y);
    }
    float bias = b_sp[o], sc = gam[o] * INV_SQRT_BN, bt = bet[o];
    float res[16];
#pragma unroll
    for (int p = 0; p < 8; p++) {
        float2 f = unpack2f(acc[p]);
        res[2 * p] = gelu_tanh(fmaf(f.x + bias, sc, bt));
        res[2 * p + 1] = gelu_tanh(fmaf(f.y + bias, sc, bt));
    }
    float* ob = out + ((size_t)b * SP_OUT + o) * N_BEF + n0;
#pragma unroll
    for (int qq = 0; qq < 4; qq++)
        *(float4*)&ob[4 * qq] = make_float4(res[4 * qq], res[4 * qq + 1], res[4 * qq + 2], res[4 * qq + 3]);
}

// ---- launcher: stream-forked overlap (kept; neutral last round) ----
extern "C" void kernel_launch(void* const* d_in, const int* in_sizes, int n_in,
                              void* d_out, int out_size) {
    const float* sparse_fea = (const float*)d_in[0];
    const float* dense_fea  = (const float*)d_in[1];
    const float* stk_coor   = (const float*)d_in[2];
    const float* stk_bef    = (const float*)d_in[3];
    const float* w_sp  = (const float*)d_in[4];
    const float* b_sp  = (const float*)d_in[5];
    const float* g_sp  = (const float*)d_in[6];
    const float* be_sp = (const float*)d_in[7];
    const float* w_ct  = (const float*)d_in[8];
    const float* b_ct  = (const float*)d_in[9];
    const float* g_dn  = (const float*)d_in[10];
    const float* be_dn = (const float*)d_in[11];
    float* out_sp = (float*)d_out;
    float* out_dn = out_sp + (size_t)BS * SP_OUT * N_BEF;

    static cudaStream_t s1 = nullptr;
    static cudaEvent_t evRoot = nullptr, evTopk = nullptr, evJoin = nullptr;
    if (!s1) {
        cudaFuncSetAttribute(k_gemm, cudaFuncAttributeMaxDynamicSharedMemorySize, SMEM_BYTES);
        cudaStreamCreateWithFlags(&s1, cudaStreamNonBlocking);
        cudaEventCreateWithFlags(&evRoot, cudaEventDisableTiming);
        cudaEventCreateWithFlags(&evTopk, cudaEventDisableTiming);
        cudaEventCreateWithFlags(&evJoin, cudaEventDisableTiming);
    }

    cudaEventRecord(evRoot, 0);
    cudaStreamWaitEvent(s1, evRoot, 0);
    k_transpose<512, 256, 1><<<dim3(8, 16, 16), dim3(32, 8), 0, s1>>>(sparse_fea);
    k_transpose<256, 512, 2><<<dim3(16, 8, 1), dim3(32, 8), 0, s1>>>(w_sp);

    k_pre<<<dim3(4, 8, 17), 256>>>(stk_coor, stk_bef);
    k_topk<<<dim3(32, 16), 256>>>(stk_bef);
    cudaEventRecord(evTopk, 0);
    cudaStreamWaitEvent(s1, evTopk, 0);
    k_sparse<<<dim3(32, 16), 256, 0, s1>>>(b_sp, g_sp, be_sp, out_sp);
    cudaEventRecord(evJoin, s1);

    k_prep<<<dim3(512, 17), 256>>>(dense_fea, w_ct);
    k_gemm<<<296, 256, SMEM_BYTES>>>(b_ct, g_dn, be_dn, out_dn);

    cudaStreamWaitEvent(0, evJoin, 0);
}

// round 14
// speedup vs baseline: 1.0407x; 1.0407x over previous
#include <cuda_runtime.h>
#include <cuda_fp16.h>
#include <cstdint>

#define BS 16
#define SP_IN 512
#define SP_OUT 256
#define DN_IN 128
#define N_STK 256
#define N_BEF 512
#define INV_SQRT_BN 0.99999500003749973f

// ---- scratch ----
__device__ float g_coorT[BS * 128 * N_STK];
__device__ float g_spT[BS * N_STK * SP_IN];
__device__ float g_wspT[SP_IN * SP_OUT];
__device__ float g_normM[BS * N_STK];
__device__ float g_normB[BS * N_BEF];
__device__ int2   g_nn[BS * N_BEF];
__device__ float2 g_wt[BS * N_BEF];
__device__ __half g_DpH[(size_t)BS * 16386 * 128];   // padded interpolated seq, HALF
__device__ unsigned g_AfragH[2 * 16384];             // [par][(s*8+mt)*32+lane]*4+r, half2 bits

// ---- helpers ----
__device__ __forceinline__ unsigned long long pack2(float a, float b) {
    unsigned long long r; asm("mov.b64 %0, {%1, %2};" : "=l"(r) : "f"(a), "f"(b)); return r;
}
__device__ __forceinline__ float2 unpack2f(unsigned long long v) {
    float2 r; asm("mov.b64 {%0, %1}, %2;" : "=f"(r.x), "=f"(r.y) : "l"(v)); return r;
}
__device__ __forceinline__ void ffma2(unsigned long long &acc, unsigned long long a, unsigned long long b) {
    asm("fma.rn.f32x2 %0, %1, %2, %0;" : "+l"(acc) : "l"(a), "l"(b));
}
__device__ __forceinline__ unsigned mono(float f) {
    unsigned u = __float_as_uint(f); return (u & 0x80000000u) ? ~u : (u | 0x80000000u);
}
__device__ __forceinline__ float invmono(unsigned u) {
    unsigned v = (u & 0x80000000u) ? (u & 0x7FFFFFFFu) : ~u; return __uint_as_float(v);
}
__device__ __forceinline__ float gelu_tanh(float x) {
    float g = 0.7978845608028654f * x * fmaf(0.044715f, x * x, 1.0f);
    float e = __expf(2.0f * g);
    return 0.5f * x * (2.0f - 2.0f / (e + 1.0f));
}
__device__ __forceinline__ void mma_f16(float* d, const uint32_t* a, uint32_t b0, uint32_t b1) {
    asm volatile("mma.sync.aligned.m16n8k16.row.col.f32.f16.f16.f32 "
                 "{%0,%1,%2,%3}, {%4,%5,%6,%7}, {%8,%9}, {%0,%1,%2,%3};"
                 : "+f"(d[0]), "+f"(d[1]), "+f"(d[2]), "+f"(d[3])
                 : "r"(a[0]), "r"(a[1]), "r"(a[2]), "r"(a[3]), "r"(b0), "r"(b1));
}
__device__ __forceinline__ uint32_t smem_u32(const void* p) {
    uint32_t a; asm("{ .reg .u64 t; cvta.to.shared.u64 t, %1; cvt.u32.u64 %0, t; }" : "=r"(a) : "l"(p)); return a;
}
__device__ __forceinline__ void cp_async16(uint32_t dst, const void* src) {
    asm volatile("cp.async.cg.shared.global [%0], [%1], 16;" :: "r"(dst), "l"(src));
}
#define CP_COMMIT() asm volatile("cp.async.commit_group;" ::: "memory")
#define CP_WAIT(n)  asm volatile("cp.async.wait_group %0;" :: "n"(n) : "memory")

// ---- merged: transpose stk_coor + both norm sets ----
__global__ void k_pre(const float* __restrict__ coor, const float* __restrict__ bef) {
    if (blockIdx.z < 16) {
        __shared__ float tile[32][33];
        int b = blockIdx.z;
        const float* s = coor + (size_t)b * 256 * 128;
        float* d = g_coorT + (size_t)b * 256 * 128;
        int r0 = blockIdx.y * 32, c0 = (blockIdx.x & 3) * 32;
        int tx = threadIdx.x & 31, ty = threadIdx.x >> 5;
#pragma unroll
        for (int k = 0; k < 32; k += 8)
            tile[ty + k][tx] = s[(size_t)(r0 + ty + k) * 128 + c0 + tx];
        __syncthreads();
#pragma unroll
        for (int k = 0; k < 32; k += 8)
            d[(size_t)(c0 + ty + k) * 256 + r0 + tx] = tile[tx][ty + k];
    } else {
        int bid = blockIdx.y * 4 + blockIdx.x;
        int warp = bid * 8 + (threadIdx.x >> 5);
        int lane = threadIdx.x & 31;
        for (int w = warp; w < BS * N_STK + BS * N_BEF; w += 256) {
            const float* src; float* dst;
            if (w < BS * N_STK) { src = coor + (size_t)w * 128; dst = g_normM + w; }
            else { int v2 = w - BS * N_STK; src = bef + (size_t)v2 * 128; dst = g_normB + v2; }
            float4 v = ((const float4*)src)[lane];
            float s = v.x * v.x + v.y * v.y + v.z * v.z + v.w * v.w;
#pragma unroll
            for (int off = 16; off; off >>= 1) s += __shfl_xor_sync(0xffffffffu, s, off);
            if (!lane) *dst = s;
        }
    }
}

// ---- top-2 neighbors (launch_bounds(256,4): verified win) ----
__global__ __launch_bounds__(256, 4) void k_topk(const float* __restrict__ bef) {
    __shared__ float befs[16 * 128];
    __shared__ unsigned long long keys[16][264];
    int n0 = blockIdx.x * 16, b = blockIdx.y, tid = threadIdx.x;
    for (int idx = tid; idx < 16 * 128; idx += 256)
        befs[idx] = bef[((size_t)b * N_BEF + n0) * 128 + idx];
    __syncthreads();
    int m = tid;
    float acc[16];
#pragma unroll
    for (int j = 0; j < 16; j++) acc[j] = 0.0f;
    const float* cT = g_coorT + (size_t)b * 128 * N_STK + m;
    for (int cb = 0; cb < 128; cb += 32) {
        float part[16];
#pragma unroll
        for (int j = 0; j < 16; j++) part[j] = 0.0f;
        for (int c0 = cb; c0 < cb + 32; c0 += 4) {
            float v0 = cT[(c0 + 0) * N_STK], v1 = cT[(c0 + 1) * N_STK];
            float v2 = cT[(c0 + 2) * N_STK], v3 = cT[(c0 + 3) * N_STK];
#pragma unroll
            for (int j = 0; j < 16; j++) {
                float4 bf = *(const float4*)&befs[j * 128 + c0];
                part[j] = fmaf(bf.x, v0, part[j]); part[j] = fmaf(bf.y, v1, part[j]);
                part[j] = fmaf(bf.z, v2, part[j]); part[j] = fmaf(bf.w, v3, part[j]);
            }
        }
#pragma unroll
        for (int j = 0; j < 16; j++) acc[j] += part[j];
    }
    float nm = g_normM[b * N_STK + m];
#pragma unroll
    for (int j = 0; j < 16; j++) {
        float d2v = g_normB[b * N_BEF + n0 + j] + nm - 2.0f * acc[j];
        keys[j][m] = ((unsigned long long)mono(d2v) << 8) | (unsigned)m;
    }
    __syncthreads();
    int wid = tid >> 5, lane = tid & 31;
#pragma unroll
    for (int jj = 0; jj < 2; jj++) {
        int j = wid + jj * 8;
        unsigned long long k1 = 0xFFFFFFFFFFFFFFFFull, k2 = k1;
#pragma unroll
        for (int t = 0; t < 8; t++) {
            unsigned long long kv = keys[j][lane * 8 + t];
            if (kv < k1) { k2 = k1; k1 = kv; }
            else if (kv < k2) { k2 = kv; }
        }
#pragma unroll
        for (int off = 16; off; off >>= 1) {
            unsigned long long o1 = __shfl_xor_sync(0xffffffffu, k1, off);
            unsigned long long o2 = __shfl_xor_sync(0xffffffffu, k2, off);
            unsigned long long n1 = k1 < o1 ? k1 : o1;
            unsigned long long hi = k1 < o1 ? o1 : k1;
            unsigned long long lo2 = k2 < o2 ? k2 : o2;
            k2 = hi < lo2 ? hi : lo2;
            k1 = n1;
        }
        if (lane == 0) {
            float d0 = invmono((unsigned)(k1 >> 8)), d1 = invmono((unsigned)(k2 >> 8));
            float r0 = 1.0f / (d0 + 1e-8f), r1 = 1.0f / (d1 + 1e-8f), s = r0 + r1;
            g_nn[b * N_BEF + n0 + j] = make_int2((int)(k1 & 0xFF), (int)(k2 & 0xFF));
            g_wt[b * N_BEF + n0 + j] = make_float2(r0 / s, r1 / s);
        }
    }
}

// ---- prepD (half output) + prepA (half fragments) merged — R11 layout ----
__global__ __launch_bounds__(256) void k_prep(const float* __restrict__ dense,
                                              const float* __restrict__ w_ct) {
    if (blockIdx.y == 16) {
        if (blockIdx.x >= 128) return;
        int idx = blockIdx.x * 256 + threadIdx.x;       // 0..32767
        int par = idx >> 14, t = idx & 16383;
        int r = t & 3, lane = (t >> 2) & 31, mt = (t >> 7) & 7, s = t >> 10;
        int g = lane >> 2, tg = lane & 3;
        int m = mt * 16 + g + ((r & 1) ? 8 : 0);
        int q = (r >= 2) ? 1 : 0;
        int c0 = s * 8 + 2 * tg;
        int tap = par ? (q ? 0 : 2) : (q ? 1 : 3);
        __half h0 = __float2half_rn(w_ct[c0 * 512 + m * 4 + tap]);
        __half h1 = __float2half_rn(w_ct[(c0 + 1) * 512 + m * 4 + tap]);
        __half2 hh = __halves2half2(h0, h1);
        g_AfragH[par * 16384 + t] = *(unsigned*)&hh;
        return;
    }
    __shared__ float sm[128 * 33];
    int n = blockIdx.x, b = blockIdx.y, tid = threadIdx.x;
    int2 id = g_nn[b * N_BEF + n]; float2 wt = g_wt[b * N_BEF + n];
    const float* dB = dense + (size_t)b * DN_IN * 8192;
    int w = tid >> 5, p = tid & 31;
    for (int c = w; c < 128; c += 8)
        sm[c * 33 + p] = wt.x * dB[c * 8192 + id.x * 32 + p] + wt.y * dB[c * 8192 + id.y * 32 + p];
    __syncthreads();
    __half2* DpRow = (__half2*)(g_DpH + ((size_t)b * 16386 + 1 + n * 32) * 128);
    for (int i = tid; i < 32 * 64; i += 256) {
        int pp = i >> 6, c2 = i & 63;
        DpRow[pp * 64 + c2] = __floats2half2_rn(sm[(2 * c2) * 33 + pp], sm[(2 * c2 + 1) * 33 + pp]);
    }
    if (n == 0 && tid < 64)
        ((__half2*)(g_DpH + (size_t)b * 16386 * 128))[tid] =
            __floats2half2_rn(sm[(2 * tid) * 33], sm[(2 * tid + 1) * 33]);
    if (n == 511 && tid < 64)
        ((__half2*)(g_DpH + ((size_t)b * 16386 + 16385) * 128))[tid] =
            __floats2half2_rn(sm[(2 * tid) * 33 + 31], sm[(2 * tid + 1) * 33 + 31]);
}

// ---- dense GEMM: mma.sync fp16 (f32 accum), persistent, cp.async x2 — R11 mainloop ----
#define STGB 272
#define STG_BYTES (66 * STGB)
#define SMEM_BYTES (65536 + 2 * STG_BYTES)
__global__ void __launch_bounds__(256, 2) k_gemm(const float* __restrict__ b_ct,
                                                 const float* __restrict__ gam,
                                                 const float* __restrict__ bet,
                                                 float* __restrict__ out) {
    extern __shared__ char smc[];
    uint4* Af4 = (uint4*)smc;
    char* stg = smc + 65536;
    int tid = threadIdx.x, wid = tid >> 5, lane = tid & 31;
    int warpM = wid & 3, warpN = wid >> 2;
    int g = lane >> 2, tg = lane & 3;
    int par = blockIdx.x & 1, cslot = blockIdx.x >> 1;

    const uint4* Ag = (const uint4*)(g_AfragH + par * 16384);
    for (int i = tid; i < 4096; i += 256) Af4[i] = Ag[i];

    float bs_[2][2], sc_[2][2], bt_[2][2];
#pragma unroll
    for (int mt = 0; mt < 2; mt++)
#pragma unroll
        for (int hh = 0; hh < 2; hh++) {
            int o = warpM * 32 + mt * 16 + g + hh * 8;
            bs_[mt][hh] = b_ct[o];
            sc_[mt][hh] = gam[o] * INV_SQRT_BN;
            bt_[mt][hh] = bet[o];
        }
    int rowb[4];
#pragma unroll
    for (int nt = 0; nt < 4; nt++)
        rowb[nt] = (warpN * 32 + nt * 8 + g + par) * STGB;

    uint32_t stg_u = smem_u32(stg);
    {
        int T = cslot, b = T >> 8, j0 = (T & 255) << 6;
        const char* src = (const char*)(g_DpH + ((size_t)b * 16386 + j0) * 128);
        for (int i = tid; i < 1056; i += 256) {
            int r = i >> 4, ck = i & 15;
            cp_async16(stg_u + r * STGB + ck * 16, src + r * 256 + ck * 16);
        }
        CP_COMMIT();
    }
    __syncthreads();

    int buf = 0;
    for (int T = cslot; T < 4096; T += 148) {
        int b = T >> 8, j0 = (T & 255) << 6;
        int Tn = T + 148;
        if (Tn < 4096) {
            int bn = Tn >> 8, j0n = (Tn & 255) << 6;
            const char* srcn = (const char*)(g_DpH + ((size_t)bn * 16386 + j0n) * 128);
            uint32_t du = stg_u + (buf ^ 1) * STG_BYTES;
            for (int i = tid; i < 1056; i += 256) {
                int r = i >> 4, ck = i & 15;
                cp_async16(du + r * STGB + ck * 16, srcn + r * 256 + ck * 16);
            }
            CP_COMMIT();
            CP_WAIT(1);
        } else {
            CP_WAIT(0);
        }
        __syncthreads();
        const char* sb = stg + buf * STG_BYTES;

        float acc[2][4][4];
#pragma unroll
        for (int mt = 0; mt < 2; mt++)
#pragma unroll
            for (int nt = 0; nt < 4; nt++)
#pragma unroll
                for (int r = 0; r < 4; r++) acc[mt][nt][r] = 0.0f;

#pragma unroll 4
        for (int s = 0; s < 16; s++) {
            uint32_t a[2][4];
            *(uint4*)a[0] = Af4[(s * 8 + warpM * 2 + 0) * 32 + lane];
            *(uint4*)a[1] = Af4[(s * 8 + warpM * 2 + 1) * 32 + lane];
            int koff = 16 * s + 4 * tg;
            uint32_t bf[4][2];
#pragma unroll
            for (int nt = 0; nt < 4; nt++) {
                bf[nt][0] = *(const uint32_t*)(sb + rowb[nt] + koff);
                bf[nt][1] = *(const uint32_t*)(sb + rowb[nt] + STGB + koff);
            }
#pragma unroll
            for (int mt = 0; mt < 2; mt++)
#pragma unroll
                for (int nt = 0; nt < 4; nt++)
                    mma_f16(acc[mt][nt], a[mt], bf[nt][0], bf[nt][1]);
        }

        float* ob = out + ((size_t)b * 128 + warpM * 32 + g) * 32768 + par;
        int jbase = j0 + warpN * 32 + tg * 2;
#pragma unroll
        for (int mt = 0; mt < 2; mt++)
#pragma unroll
            for (int nt = 0; nt < 4; nt++) {
                float* p0 = ob + (size_t)(mt * 16) * 32768 + 2 * (jbase + nt * 8);
                float* p1 = p0 + (size_t)8 * 32768;
                p0[0] = gelu_tanh(fmaf(acc[mt][nt][0] + bs_[mt][0], sc_[mt][0], bt_[mt][0]));
                p0[2] = gelu_tanh(fmaf(acc[mt][nt][1] + bs_[mt][0], sc_[mt][0], bt_[mt][0]));
                p1[0] = gelu_tanh(fmaf(acc[mt][nt][2] + bs_[mt][1], sc_[mt][1], bt_[mt][1]));
                p1[2] = gelu_tanh(fmaf(acc[mt][nt][3] + bs_[mt][1], sc_[mt][1], bt_[mt][1]));
            }
        __syncthreads();
        buf ^= 1;
    }
}

// ---- transpose (sparse branch prep) ----
template<int R, int C, int WHICH>
__global__ void k_transpose(const float* __restrict__ src) {
    float* dstbase = (WHICH == 1) ? g_spT : g_wspT;
    __shared__ float tile[32][33];
    int b = blockIdx.z;
    const float* s = src + (size_t)b * R * C;
    float* d = dstbase + (size_t)b * R * C;
    int r0 = blockIdx.y * 32, c0 = blockIdx.x * 32;
#pragma unroll
    for (int k = 0; k < 32; k += 8)
        tile[threadIdx.y + k][threadIdx.x] = s[(size_t)(r0 + threadIdx.y + k) * C + c0 + threadIdx.x];
    __syncthreads();
#pragma unroll
    for (int k = 0; k < 32; k += 8)
        d[(size_t)(c0 + threadIdx.y + k) * R + r0 + threadIdx.x] = tile[threadIdx.x][threadIdx.y + k];
}

// ---- sparse branch ----
__global__ __launch_bounds__(256) void k_sparse(const float* __restrict__ b_sp,
                                                const float* __restrict__ gam,
                                                const float* __restrict__ bet,
                                                float* __restrict__ out) {
    __shared__ float V[512 * 20];
    __shared__ int2 ii[16];
    __shared__ float2 ww[16];
    int n0 = blockIdx.x * 16, b = blockIdx.y, tid = threadIdx.x;
    if (tid < 16) { ii[tid] = g_nn[b * N_BEF + n0 + tid]; ww[tid] = g_wt[b * N_BEF + n0 + tid]; }
    __syncthreads();
    const float* sT = g_spT + (size_t)b * N_STK * SP_IN;
    for (int idx = tid; idx < 512 * 16; idx += 256) {
        int j = idx >> 9, c = idx & 511;
        int2 id = ii[j]; float2 wt = ww[j];
        V[c * 20 + j] = wt.x * sT[(size_t)id.x * SP_IN + c] + wt.y * sT[(size_t)id.y * SP_IN + c];
    }
    __syncthreads();
    int o = tid;
    unsigned long long acc[8] = {0,0,0,0,0,0,0,0};
#pragma unroll 4
    for (int c = 0; c < 512; c++) {
        float wv = g_wspT[c * SP_OUT + o];
        unsigned long long w2 = pack2(wv, wv);
        const ulonglong2* vr = (const ulonglong2*)&V[c * 20];
        ulonglong2 p0 = vr[0], p1 = vr[1], p2 = vr[2], p3 = vr[3];
        ffma2(acc[0], w2, p0.x); ffma2(acc[1], w2, p0.y);
        ffma2(acc[2], w2, p1.x); ffma2(acc[3], w2, p1.y);
        ffma2(acc[4], w2, p2.x); ffma2(acc[5], w2, p2.y);
        ffma2(acc[6], w2, p3.x); ffma2(acc[7], w2, p3.y);
    }
    float bias = b_sp[o], sc = gam[o] * INV_SQRT_BN, bt = bet[o];
    float res[16];
#pragma unroll
    for (int p = 0; p < 8; p++) {
        float2 f = unpack2f(acc[p]);
        res[2 * p] = gelu_tanh(fmaf(f.x + bias, sc, bt));
        res[2 * p + 1] = gelu_tanh(fmaf(f.y + bias, sc, bt));
    }
    float* ob = out + ((size_t)b * SP_OUT + o) * N_BEF + n0;
#pragma unroll
    for (int qq = 0; qq < 4; qq++)
        *(float4*)&ob[4 * qq] = make_float4(res[4 * qq], res[4 * qq + 1], res[4 * qq + 2], res[4 * qq + 3]);
}

// ---- launcher: stream-forked overlap (kept; neutral) ----
extern "C" void kernel_launch(void* const* d_in, const int* in_sizes, int n_in,
                              void* d_out, int out_size) {
    const float* sparse_fea = (const float*)d_in[0];
    const float* dense_fea  = (const float*)d_in[1];
    const float* stk_coor   = (const float*)d_in[2];
    const float* stk_bef    = (const float*)d_in[3];
    const float* w_sp  = (const float*)d_in[4];
    const float* b_sp  = (const float*)d_in[5];
    const float* g_sp  = (const float*)d_in[6];
    const float* be_sp = (const float*)d_in[7];
    const float* w_ct  = (const float*)d_in[8];
    const float* b_ct  = (const float*)d_in[9];
    const float* g_dn  = (const float*)d_in[10];
    const float* be_dn = (const float*)d_in[11];
    float* out_sp = (float*)d_out;
    float* out_dn = out_sp + (size_t)BS * SP_OUT * N_BEF;

    static cudaStream_t s1 = nullptr;
    static cudaEvent_t evRoot = nullptr, evTopk = nullptr, evJoin = nullptr;
    if (!s1) {
        cudaFuncSetAttribute(k_gemm, cudaFuncAttributeMaxDynamicSharedMemorySize, SMEM_BYTES);
        cudaStreamCreateWithFlags(&s1, cudaStreamNonBlocking);
        cudaEventCreateWithFlags(&evRoot, cudaEventDisableTiming);
        cudaEventCreateWithFlags(&evTopk, cudaEventDisableTiming);
        cudaEventCreateWithFlags(&evJoin, cudaEventDisableTiming);
    }

    cudaEventRecord(evRoot, 0);
    cudaStreamWaitEvent(s1, evRoot, 0);
    k_transpose<512, 256, 1><<<dim3(8, 16, 16), dim3(32, 8), 0, s1>>>(sparse_fea);
    k_transpose<256, 512, 2><<<dim3(16, 8, 1), dim3(32, 8), 0, s1>>>(w_sp);

    k_pre<<<dim3(4, 8, 17), 256>>>(stk_coor, stk_bef);
    k_topk<<<dim3(32, 16), 256>>>(stk_bef);
    cudaEventRecord(evTopk, 0);
    cudaStreamWaitEvent(s1, evTopk, 0);
    k_sparse<<<dim3(32, 16), 256, 0, s1>>>(b_sp, g_sp, be_sp, out_sp);
    cudaEventRecord(evJoin, s1);

    k_prep<<<dim3(512, 17), 256>>>(dense_fea, w_ct);
    k_gemm<<<296, 256, SMEM_BYTES>>>(b_ct, g_dn, be_dn, out_dn);

    cudaStreamWaitEvent(0, evJoin, 0);
}